// round 15
// baseline (speedup 1.0000x reference)
#include <cuda_runtime.h>
#include <cuda_fp16.h>
#include <cstdint>

// lct_fk round 15: R14 (176.6us) with
//  (a) all three t_samp launches merged into ONE kernel (grid.y=130):
//      y<127 Hermitian pair path, y=127/128 direct planes h=128/129,
//      y=129 packed exception columns (h in {1,130..255}, x in {128,129}).
//      Single-writer coverage identical to R14; no serial micro-launch tails.
//  (b) k_fwd_x pair-filter via lane shuffles (j is lane-contiguous there),
//      deleting the second smem staging round trip. Exact same arithmetic.

#define LL 256u
#define VOLS 2

__device__ __half2 g_A[(size_t)VOLS * LL * LL * LL]; // 134 MB

__device__ const int BR4[16] = {0,8,4,12,2,10,6,14,1,9,5,13,3,11,7,15};

__device__ __forceinline__ float2 h2f(__half2 h) { return __half22float2(h); }
__device__ __forceinline__ __half2 f2h(float2 f) { return __floats2half2_rn(f.x, f.y); }

// ---------------- 16-pt in-register DIT FFT (input bit-reversed) ------------
template<bool ZIN, bool HOUT>
__device__ __forceinline__ void fft16x(float2 r[16], float dir) {
    const float CT[8] = {1.f, 0.92387953f, 0.70710678f, 0.38268343f,
                         0.f, -0.38268343f, -0.70710678f, -0.92387953f};
    const float ST[8] = {0.f, -0.38268343f, -0.70710678f, -0.92387953f,
                         -1.f, -0.92387953f, -0.70710678f, -0.38268343f};
    if (ZIN) {
#pragma unroll
        for (int m = 0; m < 8; ++m) r[2 * m + 1] = r[2 * m];
    } else {
#pragma unroll
        for (int m = 0; m < 8; ++m) {
            float2 a = r[2 * m], b = r[2 * m + 1];
            r[2 * m]     = make_float2(a.x + b.x, a.y + b.y);
            r[2 * m + 1] = make_float2(a.x - b.x, a.y - b.y);
        }
    }
#pragma unroll
    for (int s = 2; s <= 3; ++s) {
        int half = 1 << (s - 1);
#pragma unroll
        for (int j = 0; j < 8; ++j) {
            int k = j & (half - 1);
            int i0 = ((j >> (s - 1)) << s) + k;
            int i1 = i0 + half;
            float cs = CT[k << (4 - s)];
            float sn = dir * ST[k << (4 - s)];
            float2 b = r[i1];
            float tx = b.x * cs - b.y * sn;
            float ty = b.x * sn + b.y * cs;
            float2 a = r[i0];
            r[i1] = make_float2(a.x - tx, a.y - ty);
            r[i0] = make_float2(a.x + tx, a.y + ty);
        }
    }
#pragma unroll
    for (int j = 0; j < 8; ++j) {
        float cs = CT[j];
        float sn = dir * ST[j];
        float2 b = r[j + 8];
        float tx = b.x * cs - b.y * sn;
        float ty = b.x * sn + b.y * cs;
        float2 a = r[j];
        r[j] = make_float2(a.x + tx, a.y + ty);
        if (!HOUT) r[j + 8] = make_float2(a.x - tx, a.y - ty);
    }
}

// inter-pass twiddle via recurrence: r[k1] *= exp(dir * -2*pi*i * j*k1/256)
__device__ __forceinline__ void twiddle16(float2 r[16], int j, float dir) {
    float wy, wx;
    __sincosf(dir * -0.024543692606f * (float)j, &wy, &wx);
    float cx = wx, cy = wy;
#pragma unroll
    for (int k1 = 1; k1 < 16; ++k1) {
        float2 a = r[k1];
        r[k1] = make_float2(a.x * cx - a.y * cy, a.x * cy + a.y * cx);
        float nx = cx * wx - cy * wy;
        float ny = cx * wy + cy * wx;
        cx = nx; cy = ny;
    }
}

// Full 256-pt FFT for one line handled by 16 threads (role j).
template<bool ZIN, bool HOUT>
__device__ __forceinline__ void fft256_pass(float2 r[16], float2* Tline,
                                            int j, float dir) {
    fft16x<ZIN, false>(r, dir);
    twiddle16(r, j, dir);
    __syncthreads();
#pragma unroll
    for (int k1 = 0; k1 < 16; ++k1) Tline[k1 * 17 + j] = r[k1];
    __syncthreads();
    float2 rr[16];
#pragma unroll
    for (int n2 = 0; n2 < 16; ++n2) rr[BR4[n2]] = Tline[j * 17 + n2];
    fft16x<false, HOUT>(rr, dir);
#pragma unroll
    for (int k = 0; k < (HOUT ? 8 : 16); ++k) r[k] = rr[k];
}

// ------- Pass 1: preprocess + x-FFT + x-filter (filter via lane shfl) -------
__global__ void k_fwd_x(const float* __restrict__ in) {
    __shared__ float2 T[16][273];
    int tid = threadIdx.x;
    int j = tid & 15, ln = tid >> 4;     // j is lane-contiguous (16-lane segs)
    unsigned h = blockIdx.x * 16 + ln, t = blockIdx.y, v = blockIdx.z;
    float g = (float)t * (1.0f / 127.0f);
    const float* src = in + (((v * 128u + t) * 128u + h) * 128u);
    float2 r[16];
#pragma unroll
    for (int n1 = 0; n1 < 8; ++n1) {
        float f = src[16 * n1 + j];
        float xx = f * g * g;
        float val = (xx > 0.0f) ? sqrtf(xx) : 0.0f;
        r[BR4[n1]] = make_float2(val, 0.0f);
    }
    fft256_pass<true, false>(r, T[ln], j, 1.0f);
    __half2* __restrict__ dst = g_A + (((v * LL + t) * LL + h) * LL);
    int src_lane = (j + 15) & 15;
#pragma unroll
    for (int k2 = 0; k2 < 16; ++k2) {
        // X[k-1]: lane j-1's r[k2]; lane 0 wraps to lane 15's r[(k2-1)&15]
        float2 mine = (j == 15) ? r[(k2 + 15) & 15] : r[k2];
        float2 b;
        b.x = __shfl_sync(0xFFFFFFFFu, mine.x, src_lane, 16);
        b.y = __shfl_sync(0xFFFFFFFFu, mine.y, src_lane, 16);
        if (j == 0 && k2 == 8) { b.x = 0.f; b.y = 0.f; }   // k == 128 exception
        dst[j + 16 * k2] =
            f2h(make_float2(0.5f * (r[k2].x + b.x), 0.5f * (r[k2].y + b.y)));
    }
}

// ---------------- Pass 2: h-FFT (reads h<128) + y-filter, writes all h ------
__global__ void k_fwd_h() {
    __shared__ float2 T[16][273];
    int tid = threadIdx.x;
    int tx = tid & 15, j = tid >> 4;
    unsigned x = blockIdx.x * 16 + tx, t = blockIdx.y, v = blockIdx.z;
    unsigned base = (v * LL + t) * LL * LL + x;
    float2 r[16];
#pragma unroll
    for (int n1 = 0; n1 < 8; ++n1) {
        unsigned hh = 16 * n1 + j;
        r[BR4[n1]] = h2f(g_A[base + hh * LL]);
    }
    fft256_pass<true, false>(r, T[tx], j, 1.0f);
    __syncthreads();
#pragma unroll
    for (int k2 = 0; k2 < 16; ++k2) T[tx][j + 17 * k2] = r[k2];
    __syncthreads();
#pragma unroll
    for (int k2 = 0; k2 < 16; ++k2) {
        int k = j + 16 * k2;
        float2 a = T[tx][k + (k >> 4)];
        float2 b = make_float2(0.f, 0.f);
        if (k != 128) { int km = (k - 1) & 255; b = T[tx][km + (km >> 4)]; }
        g_A[base + (unsigned)k * LL] =
            f2h(make_float2(0.5f * (a.x + b.x), 0.5f * (a.y + b.y)));
    }
}

// ---- Pass 3 (merged): Hermitian pair path + exception direct paths ---------
__global__ void k_t_samp() {
    __shared__ float2 T[16][273];
    __shared__ float2 S2[16][137];
    int tid = threadIdx.x;
    int tx = tid & 15, j = tid >> 4;
    unsigned v = blockIdx.z;
    unsigned y = blockIdx.y;
    const float SC = 1.0f / 4096.0f;

    if (y < 127u) {
        // ======== pair path: base hb in {0,2..127}, mirror (257-hb,257-x) ===
        unsigned x = blockIdx.x * 16 + tx;
        unsigned hb = (y == 0) ? 0u : (y + 1u);
        unsigned base = v * LL * LL * LL + hb * LL + x;

        float2 r[16];
#pragma unroll
        for (int n1 = 0; n1 < 8; ++n1)
            r[BR4[n1]] = h2f(g_A[base + (unsigned)(16 * n1 + j) * (LL * LL)]);
        fft256_pass<true, false>(r, T[tx], j, 1.0f);   // FULL spectrum
        __syncthreads();
#pragma unroll
        for (int k2 = 0; k2 < 16; ++k2) {
            int k = j + 16 * k2;
            T[tx][k + (k >> 4)] = r[k2];
        }
        __syncthreads();

        int iy = ((int)hb + 128) & 255;
        int ixs = ((int)x + 128) & 255;
        float gx = (float)(ixs - 128) * (1.0f / 128.0f);
        float gy = (float)(iy - 128) * (1.0f / 128.0f);
        float rxy = 0.1024f * (gx * gx + gy * gy);
        unsigned hm = (257u - hb) & 255u;
        unsigned xm = (257u - x) & 255u;
        int iym = ((int)hm + 128) & 255;
        int ixm = ((int)xm + 128) & 255;
        float gxm = (float)(ixm - 128) * (1.0f / 128.0f);
        float gym = (float)(iym - 128) * (1.0f / 128.0f);
        float rxym = 0.1024f * (gxm * gxm + gym * gym);

#pragma unroll
        for (int n1 = 0; n1 < 8; ++n1) {
            int t = 16 * n1 + j;
            float2 s = make_float2(0.f, 0.f);
            float2 sm = make_float2(0.f, 0.f);
            if (t >= 1) {
                float gz = (float)t * (1.0f / 128.0f);
                {   // base
                    float q = rxy + gz * gz;
                    float rq = rsqrtf(q);
                    float pzf = 128.0f * (q * rq) + 127.5f;
                    int z0 = (int)pzf;
                    float dz = pzf - (float)z0;
                    int p0 = z0 - 128, p1 = z0 - 127;
                    float sc = gz * rq;
                    float2 F0 = (p0 <= 127) ? T[tx][p0 + (p0 >> 4)] : make_float2(0.f, 0.f);
                    float2 F1 = (p1 <= 127) ? T[tx][p1 + (p1 >> 4)] : make_float2(0.f, 0.f);
                    s = make_float2((F0.x * (1.f - dz) + F1.x * dz) * sc,
                                    (F0.y * (1.f - dz) + F1.y * dz) * sc);
                }
                {   // mirror: F_mir[p] = conj(F[(256-p)&255]), own rxy
                    float q = rxym + gz * gz;
                    float rq = rsqrtf(q);
                    float pzf = 128.0f * (q * rq) + 127.5f;
                    int z0 = (int)pzf;
                    float dz = pzf - (float)z0;
                    int p0 = z0 - 128, p1 = z0 - 127;
                    float sc = gz * rq;
                    int m0 = (256 - p0) & 255;
                    int m1 = (256 - p1) & 255;
                    float2 F0 = (p0 <= 127) ? T[tx][m0 + (m0 >> 4)] : make_float2(0.f, 0.f);
                    float2 F1 = (p1 <= 127) ? T[tx][m1 + (m1 >> 4)] : make_float2(0.f, 0.f);
                    sm = make_float2((F0.x * (1.f - dz) + F1.x * dz) * sc,
                                     -(F0.y * (1.f - dz) + F1.y * dz) * sc);
                }
            }
            r[BR4[n1]] = s;
            S2[tx][t + (t >> 4)] = sm;
        }
        fft256_pass<true, true>(r, T[tx], j, -1.0f);
#pragma unroll
        for (int k2 = 0; k2 < 8; ++k2)
            g_A[base + (unsigned)(j + 16 * k2) * (LL * LL)] =
                f2h(make_float2(r[k2].x * SC, r[k2].y * SC));

#pragma unroll
        for (int n1 = 0; n1 < 8; ++n1) {
            int t = 16 * n1 + j;
            r[BR4[n1]] = S2[tx][t + (t >> 4)];
        }
        fft256_pass<true, true>(r, T[tx], j, -1.0f);
        if (x != 128u && x != 129u) {
            unsigned baseM = v * LL * LL * LL + hm * LL + xm;
#pragma unroll
            for (int k2 = 0; k2 < 8; ++k2)
                g_A[baseM + (unsigned)(j + 16 * k2) * (LL * LL)] =
                    f2h(make_float2(r[k2].x * SC, r[k2].y * SC));
        }
    } else {
        // ======== direct paths (exception columns) ==========================
        unsigned x, h;
        bool store;
        if (y < 129u) {                    // y=127 -> h=128, y=128 -> h=129
            h = y + 1u;
            x = blockIdx.x * 16 + tx;
            store = true;
        } else {                           // y=129: packed (h,x) exceptions
            int c = (int)(blockIdx.x * 16) + tx;   // 0..255
            int hidx = c >> 1;                     // 0..127
            h = (hidx == 0) ? 1u : (129u + (unsigned)hidx); // 1,130..255
            x = 128u + (unsigned)(c & 1);
            store = (c < 254);
            if (hidx > 126) h = 1u;                // harmless clamp, store off
        }
        unsigned base = v * LL * LL * LL + h * LL + x;

        float2 r[16];
#pragma unroll
        for (int n1 = 0; n1 < 8; ++n1)
            r[BR4[n1]] = h2f(g_A[base + (unsigned)(16 * n1 + j) * (LL * LL)]);
        fft256_pass<true, true>(r, T[tx], j, 1.0f);
        __syncthreads();
#pragma unroll
        for (int k2 = 0; k2 < 8; ++k2) {
            int k = j + 16 * k2;
            T[tx][k + (k >> 4)] = r[k2];
        }
        __syncthreads();

        int iy = ((int)h + 128) & 255;
        int ixs = ((int)x + 128) & 255;
        float gx = (float)(ixs - 128) * (1.0f / 128.0f);
        float gy = (float)(iy - 128) * (1.0f / 128.0f);
        float rxy = 0.1024f * (gx * gx + gy * gy);

#pragma unroll
        for (int n1 = 0; n1 < 8; ++n1) {
            int t = 16 * n1 + j;
            float2 s = make_float2(0.f, 0.f);
            if (t >= 1) {
                float gz = (float)t * (1.0f / 128.0f);
                float q = rxy + gz * gz;
                float rq = rsqrtf(q);
                float pzf = 128.0f * (q * rq) + 127.5f;
                int z0 = (int)pzf;
                float dz = pzf - (float)z0;
                int p0 = z0 - 128, p1 = z0 - 127;
                float2 S0 = (p0 <= 127) ? T[tx][p0 + (p0 >> 4)] : make_float2(0.f, 0.f);
                float2 S1 = (p1 <= 127) ? T[tx][p1 + (p1 >> 4)] : make_float2(0.f, 0.f);
                float sc = gz * rq;
                s = make_float2((S0.x * (1.f - dz) + S1.x * dz) * sc,
                                (S0.y * (1.f - dz) + S1.y * dz) * sc);
            }
            r[BR4[n1]] = s;
        }
        fft256_pass<true, true>(r, T[tx], j, -1.0f);
        if (store) {
#pragma unroll
            for (int k2 = 0; k2 < 8; ++k2)
                g_A[base + (unsigned)(j + 16 * k2) * (LL * LL)] =
                    f2h(make_float2(r[k2].x * SC, r[k2].y * SC));
        }
    }
}

// ---------------- Pass 4: inverse h-FFT (reads all h, writes h<128) ---------
__global__ void k_inv_h() {
    __shared__ float2 T[16][273];
    int tid = threadIdx.x;
    int tx = tid & 15, j = tid >> 4;
    unsigned x = blockIdx.x * 16 + tx, t = blockIdx.y, v = blockIdx.z;
    unsigned base = (v * LL + t) * LL * LL + x;
    float2 r[16];
#pragma unroll
    for (int n1 = 0; n1 < 16; ++n1)
        r[BR4[n1]] = h2f(g_A[base + (unsigned)(16 * n1 + j) * LL]);
    fft256_pass<false, true>(r, T[tx], j, -1.0f);
    const float SC = 1.0f / 4096.0f;
#pragma unroll
    for (int k2 = 0; k2 < 8; ++k2)
        g_A[base + (unsigned)(j + 16 * k2) * LL] =
            f2h(make_float2(r[k2].x * SC, r[k2].y * SC));
}

// ---------------- Pass 5: inverse x-FFT + real crop ------------------------
__global__ void k_inv_x(float* __restrict__ out) {
    __shared__ float2 T[16][273];
    int tid = threadIdx.x;
    int j = tid & 15, ln = tid >> 4;
    unsigned h = blockIdx.x * 16 + ln, t = blockIdx.y, v = blockIdx.z;
    unsigned base = ((v * LL + t) * LL + h) * LL;
    float2 r[16];
#pragma unroll
    for (int n1 = 0; n1 < 16; ++n1)
        r[BR4[n1]] = h2f(g_A[base + 16 * n1 + j]);
    fft256_pass<false, true>(r, T[ln], j, -1.0f);
    float* dst = out + (((v * 128u + t) * 128u + h) * 128u);
#pragma unroll
    for (int k2 = 0; k2 < 8; ++k2)
        dst[j + 16 * k2] = r[k2].x;
}

extern "C" void kernel_launch(void* const* d_in, const int* in_sizes, int n_in,
                              void* d_out, int out_size) {
    (void)in_sizes; (void)n_in; (void)out_size;
    const float* in = (const float*)d_in[0];
    float* out = (float*)d_out;

    k_fwd_x<<<dim3(8, 128, VOLS), 256>>>(in);
    k_fwd_h<<<dim3(16, 128, VOLS), 256>>>();
    k_t_samp<<<dim3(16, 130, VOLS), 256>>>();
    k_inv_h<<<dim3(16, 128, VOLS), 256>>>();
    k_inv_x<<<dim3(8, 128, VOLS), 256>>>(out);
}

// round 16
// speedup vs baseline: 1.0846x; 1.0846x over previous
#include <cuda_runtime.h>
#include <cuda_fp16.h>
#include <cstdint>

// lct_fk round 16: R14 base (176.6us) + forward-pass Hermitian folding.
//  - fwd_x writes only kx<=129 (nothing else is read downstream).
//  - fwd_h processes x in 0..143 only; for x in 2..127 the mirror column
//    x'=257-x is written directly from the same h-spectrum using
//    F_h[k,x'] = conj(F_h[(256-k)&255,x]) (exact: col(x') = conj(col(x))),
//    with filter-exception cases k'=128 -> conj(0.5*F128),
//    k'=129 -> conj(0.5*(F127+F128)). Writes only h-planes k<=129
//    (+ full k for x in {128,129}), matching exactly what t_samp reads.
//  t_samp / inv_h / inv_x identical to R14. Single-writer everywhere.

#define LL 256u
#define VOLS 2

__device__ __half2 g_A[(size_t)VOLS * LL * LL * LL]; // 134 MB

__device__ const int BR4[16] = {0,8,4,12,2,10,6,14,1,9,5,13,3,11,7,15};

__device__ __forceinline__ float2 h2f(__half2 h) { return __half22float2(h); }
__device__ __forceinline__ __half2 f2h(float2 f) { return __floats2half2_rn(f.x, f.y); }

// ---------------- 16-pt in-register DIT FFT (input bit-reversed) ------------
template<bool ZIN, bool HOUT>
__device__ __forceinline__ void fft16x(float2 r[16], float dir) {
    const float CT[8] = {1.f, 0.92387953f, 0.70710678f, 0.38268343f,
                         0.f, -0.38268343f, -0.70710678f, -0.92387953f};
    const float ST[8] = {0.f, -0.38268343f, -0.70710678f, -0.92387953f,
                         -1.f, -0.92387953f, -0.70710678f, -0.38268343f};
    if (ZIN) {
#pragma unroll
        for (int m = 0; m < 8; ++m) r[2 * m + 1] = r[2 * m];
    } else {
#pragma unroll
        for (int m = 0; m < 8; ++m) {
            float2 a = r[2 * m], b = r[2 * m + 1];
            r[2 * m]     = make_float2(a.x + b.x, a.y + b.y);
            r[2 * m + 1] = make_float2(a.x - b.x, a.y - b.y);
        }
    }
#pragma unroll
    for (int s = 2; s <= 3; ++s) {
        int half = 1 << (s - 1);
#pragma unroll
        for (int j = 0; j < 8; ++j) {
            int k = j & (half - 1);
            int i0 = ((j >> (s - 1)) << s) + k;
            int i1 = i0 + half;
            float cs = CT[k << (4 - s)];
            float sn = dir * ST[k << (4 - s)];
            float2 b = r[i1];
            float tx = b.x * cs - b.y * sn;
            float ty = b.x * sn + b.y * cs;
            float2 a = r[i0];
            r[i1] = make_float2(a.x - tx, a.y - ty);
            r[i0] = make_float2(a.x + tx, a.y + ty);
        }
    }
#pragma unroll
    for (int j = 0; j < 8; ++j) {
        float cs = CT[j];
        float sn = dir * ST[j];
        float2 b = r[j + 8];
        float tx = b.x * cs - b.y * sn;
        float ty = b.x * sn + b.y * cs;
        float2 a = r[j];
        r[j] = make_float2(a.x + tx, a.y + ty);
        if (!HOUT) r[j + 8] = make_float2(a.x - tx, a.y - ty);
    }
}

// inter-pass twiddle via recurrence: r[k1] *= exp(dir * -2*pi*i * j*k1/256)
__device__ __forceinline__ void twiddle16(float2 r[16], int j, float dir) {
    float wy, wx;
    __sincosf(dir * -0.024543692606f * (float)j, &wy, &wx);
    float cx = wx, cy = wy;
#pragma unroll
    for (int k1 = 1; k1 < 16; ++k1) {
        float2 a = r[k1];
        r[k1] = make_float2(a.x * cx - a.y * cy, a.x * cy + a.y * cx);
        float nx = cx * wx - cy * wy;
        float ny = cx * wy + cy * wx;
        cx = nx; cy = ny;
    }
}

// Full 256-pt FFT for one line handled by 16 threads (role j).
template<bool ZIN, bool HOUT>
__device__ __forceinline__ void fft256_pass(float2 r[16], float2* Tline,
                                            int j, float dir) {
    fft16x<ZIN, false>(r, dir);
    twiddle16(r, j, dir);
    __syncthreads();
#pragma unroll
    for (int k1 = 0; k1 < 16; ++k1) Tline[k1 * 17 + j] = r[k1];
    __syncthreads();
    float2 rr[16];
#pragma unroll
    for (int n2 = 0; n2 < 16; ++n2) rr[BR4[n2]] = Tline[j * 17 + n2];
    fft16x<false, HOUT>(rr, dir);
#pragma unroll
    for (int k = 0; k < (HOUT ? 8 : 16); ++k) r[k] = rr[k];
}

// ---------------- Pass 1: preprocess + x-FFT + x-filter (kx<=129 only) ------
__global__ void k_fwd_x(const float* __restrict__ in) {
    __shared__ float2 T[16][273];
    int tid = threadIdx.x;
    int j = tid & 15, ln = tid >> 4;
    unsigned h = blockIdx.x * 16 + ln, t = blockIdx.y, v = blockIdx.z;
    float g = (float)t * (1.0f / 127.0f);
    const float* src = in + (((v * 128u + t) * 128u + h) * 128u);
    float2 r[16];
#pragma unroll
    for (int n1 = 0; n1 < 8; ++n1) {
        float f = src[16 * n1 + j];
        float xx = f * g * g;
        float val = (xx > 0.0f) ? sqrtf(xx) : 0.0f;
        r[BR4[n1]] = make_float2(val, 0.0f);
    }
    fft256_pass<true, false>(r, T[ln], j, 1.0f);
    __syncthreads();
#pragma unroll
    for (int k2 = 0; k2 < 16; ++k2) T[ln][j + 17 * k2] = r[k2];
    __syncthreads();
    __half2* __restrict__ dst = g_A + (((v * LL + t) * LL + h) * LL);
#pragma unroll
    for (int k2 = 0; k2 < 9; ++k2) {
        int k = j + 16 * k2;
        if (k > 129) continue;             // downstream reads only kx<=129
        float2 a = T[ln][k + (k >> 4)];
        float2 b = make_float2(0.f, 0.f);
        if (k != 128) { int km = (k - 1) & 255; b = T[ln][km + (km >> 4)]; }
        dst[k] = f2h(make_float2(0.5f * (a.x + b.x), 0.5f * (a.y + b.y)));
    }
}

// --- Pass 2: h-FFT for x in 0..143; base writes k<=129 (x=128/129: all k); --
// --- mirror columns x'=257-x (x in 2..127) written from same spectrum. ------
__global__ void k_fwd_h() {
    __shared__ float2 T[16][273];
    int tid = threadIdx.x;
    int tx = tid & 15, j = tid >> 4;
    unsigned x = blockIdx.x * 16 + tx;    // grid.x = 9 -> x in 0..143
    unsigned t = blockIdx.y, v = blockIdx.z;
    unsigned base = (v * LL + t) * LL * LL + x;
    float2 r[16];
#pragma unroll
    for (int n1 = 0; n1 < 8; ++n1)
        r[BR4[n1]] = h2f(g_A[base + (unsigned)(16 * n1 + j) * LL]);
    fft256_pass<true, false>(r, T[tx], j, 1.0f);
    __syncthreads();
#pragma unroll
    for (int k2 = 0; k2 < 16; ++k2) T[tx][j + 17 * k2] = r[k2]; // stash F
    __syncthreads();

    bool fullk = (x == 128u || x == 129u);
    bool basew = (x <= 129u);
#pragma unroll
    for (int k2 = 0; k2 < 16; ++k2) {
        int k = j + 16 * k2;
        bool wr = fullk || (basew && k <= 129);
        if (!wr) continue;
        float2 a = T[tx][k + (k >> 4)];
        float2 b = make_float2(0.f, 0.f);
        if (k != 128) { int km = (k - 1) & 255; b = T[tx][km + (km >> 4)]; }
        g_A[base + (unsigned)k * LL] =
            f2h(make_float2(0.5f * (a.x + b.x), 0.5f * (a.y + b.y)));
    }

    if (x >= 2u && x <= 127u) {           // emit mirror column x' = 257-x
        unsigned xm = 257u - x;           // 130..255
        unsigned baseM = (v * LL + t) * LL * LL + xm;
#pragma unroll
        for (int k2 = 0; k2 < 9; ++k2) {
            int kp = j + 16 * k2;
            if (kp > 129) continue;
            float2 val;
            if (kp <= 127) {
                int m = (257 - kp) & 255;        // kp=0->1, kp=1->0, else 130..255
                int mm1 = (m - 1) & 255;
                float2 Fm = T[tx][m + (m >> 4)];
                float2 Fm1 = T[tx][mm1 + (mm1 >> 4)];
                val = make_float2(0.5f * (Fm.x + Fm1.x), -0.5f * (Fm.y + Fm1.y));
            } else if (kp == 128) {
                float2 F128 = T[tx][128 + 8];
                val = make_float2(0.5f * F128.x, -0.5f * F128.y);
            } else {                              // kp == 129
                float2 F127 = T[tx][127 + 7];
                float2 F128 = T[tx][128 + 8];
                val = make_float2(0.5f * (F127.x + F128.x),
                                  -0.5f * (F127.y + F128.y));
            }
            g_A[baseM + (unsigned)kp * LL] = f2h(val);
        }
    }
}

// ---- Pass 3a (paired): fwd t-FFT -> base+mirror Stolt -> 2x inverse --------
__global__ void k_t_samp_pair() {
    __shared__ float2 T[16][273];
    __shared__ float2 S2[16][137];
    int tid = threadIdx.x;
    int tx = tid & 15, j = tid >> 4;
    unsigned x = blockIdx.x * 16 + tx;
    unsigned hb = (blockIdx.y == 0) ? 0u : (blockIdx.y + 1u); // 0,2..127
    unsigned v = blockIdx.z;
    unsigned base = v * LL * LL * LL + hb * LL + x;

    float2 r[16];
#pragma unroll
    for (int n1 = 0; n1 < 8; ++n1)
        r[BR4[n1]] = h2f(g_A[base + (unsigned)(16 * n1 + j) * (LL * LL)]);
    fft256_pass<true, false>(r, T[tx], j, 1.0f);
    __syncthreads();
#pragma unroll
    for (int k2 = 0; k2 < 16; ++k2) {
        int k = j + 16 * k2;
        T[tx][k + (k >> 4)] = r[k2];
    }
    __syncthreads();

    int iy = ((int)hb + 128) & 255;
    int ixs = ((int)x + 128) & 255;
    float gx = (float)(ixs - 128) * (1.0f / 128.0f);
    float gy = (float)(iy - 128) * (1.0f / 128.0f);
    float rxy = 0.1024f * (gx * gx + gy * gy);
    unsigned hm = (257u - hb) & 255u;
    unsigned xm = (257u - x) & 255u;
    int iym = ((int)hm + 128) & 255;
    int ixm = ((int)xm + 128) & 255;
    float gxm = (float)(ixm - 128) * (1.0f / 128.0f);
    float gym = (float)(iym - 128) * (1.0f / 128.0f);
    float rxym = 0.1024f * (gxm * gxm + gym * gym);

#pragma unroll
    for (int n1 = 0; n1 < 8; ++n1) {
        int t = 16 * n1 + j;
        float2 s = make_float2(0.f, 0.f);
        float2 sm = make_float2(0.f, 0.f);
        if (t >= 1) {
            float gz = (float)t * (1.0f / 128.0f);
            {   // base
                float q = rxy + gz * gz;
                float rq = rsqrtf(q);
                float pzf = 128.0f * (q * rq) + 127.5f;
                int z0 = (int)pzf;
                float dz = pzf - (float)z0;
                int p0 = z0 - 128, p1 = z0 - 127;
                float sc = gz * rq;
                float2 F0 = (p0 <= 127) ? T[tx][p0 + (p0 >> 4)] : make_float2(0.f, 0.f);
                float2 F1 = (p1 <= 127) ? T[tx][p1 + (p1 >> 4)] : make_float2(0.f, 0.f);
                s = make_float2((F0.x * (1.f - dz) + F1.x * dz) * sc,
                                (F0.y * (1.f - dz) + F1.y * dz) * sc);
            }
            {   // mirror: F_mir[p] = conj(F[(256-p)&255]), own rxy
                float q = rxym + gz * gz;
                float rq = rsqrtf(q);
                float pzf = 128.0f * (q * rq) + 127.5f;
                int z0 = (int)pzf;
                float dz = pzf - (float)z0;
                int p0 = z0 - 128, p1 = z0 - 127;
                float sc = gz * rq;
                int m0 = (256 - p0) & 255;
                int m1 = (256 - p1) & 255;
                float2 F0 = (p0 <= 127) ? T[tx][m0 + (m0 >> 4)] : make_float2(0.f, 0.f);
                float2 F1 = (p1 <= 127) ? T[tx][m1 + (m1 >> 4)] : make_float2(0.f, 0.f);
                sm = make_float2((F0.x * (1.f - dz) + F1.x * dz) * sc,
                                 -(F0.y * (1.f - dz) + F1.y * dz) * sc);
            }
        }
        r[BR4[n1]] = s;
        S2[tx][t + (t >> 4)] = sm;
    }
    fft256_pass<true, true>(r, T[tx], j, -1.0f);

    const float SC = 1.0f / 4096.0f;
#pragma unroll
    for (int k2 = 0; k2 < 8; ++k2)
        g_A[base + (unsigned)(j + 16 * k2) * (LL * LL)] =
            f2h(make_float2(r[k2].x * SC, r[k2].y * SC));

#pragma unroll
    for (int n1 = 0; n1 < 8; ++n1) {
        int t = 16 * n1 + j;
        r[BR4[n1]] = S2[tx][t + (t >> 4)];
    }
    fft256_pass<true, true>(r, T[tx], j, -1.0f);
    if (x != 128u && x != 129u) {
        unsigned baseM = v * LL * LL * LL + hm * LL + xm;
#pragma unroll
        for (int k2 = 0; k2 < 8; ++k2)
            g_A[baseM + (unsigned)(j + 16 * k2) * (LL * LL)] =
                f2h(make_float2(r[k2].x * SC, r[k2].y * SC));
    }
}

// ---- Pass 3b (direct): exception columns ----------------------------------
__global__ void k_t_samp_direct(int hsel) {
    __shared__ float2 T[16][273];
    int tid = threadIdx.x;
    int tx = tid & 15, j = tid >> 4;
    unsigned x = (hsel ? 128u : blockIdx.x * 16u) + tx;
    unsigned h = hsel ? ((blockIdx.y == 0) ? 1u : (129u + blockIdx.y))
                      : (128u + blockIdx.y);
    unsigned v = blockIdx.z;
    unsigned base = v * LL * LL * LL + h * LL + x;
    bool do_store = (hsel == 0) || (tx < 2);

    float2 r[16];
#pragma unroll
    for (int n1 = 0; n1 < 8; ++n1)
        r[BR4[n1]] = h2f(g_A[base + (unsigned)(16 * n1 + j) * (LL * LL)]);
    fft256_pass<true, true>(r, T[tx], j, 1.0f);

    __syncthreads();
#pragma unroll
    for (int k2 = 0; k2 < 8; ++k2) {
        int k = j + 16 * k2;
        T[tx][k + (k >> 4)] = r[k2];
    }
    __syncthreads();

    int iy = ((int)h + 128) & 255;
    int ixs = ((int)x + 128) & 255;
    float gx = (float)(ixs - 128) * (1.0f / 128.0f);
    float gy = (float)(iy - 128) * (1.0f / 128.0f);
    float rxy = 0.1024f * (gx * gx + gy * gy);

#pragma unroll
    for (int n1 = 0; n1 < 8; ++n1) {
        int t = 16 * n1 + j;
        float2 s = make_float2(0.f, 0.f);
        if (t >= 1) {
            float gz = (float)t * (1.0f / 128.0f);
            float q = rxy + gz * gz;
            float rq = rsqrtf(q);
            float pzf = 128.0f * (q * rq) + 127.5f;
            int z0 = (int)pzf;
            float dz = pzf - (float)z0;
            int p0 = z0 - 128, p1 = z0 - 127;
            float2 S0 = (p0 <= 127) ? T[tx][p0 + (p0 >> 4)] : make_float2(0.f, 0.f);
            float2 S1 = (p1 <= 127) ? T[tx][p1 + (p1 >> 4)] : make_float2(0.f, 0.f);
            float sc = gz * rq;
            s = make_float2((S0.x * (1.f - dz) + S1.x * dz) * sc,
                            (S0.y * (1.f - dz) + S1.y * dz) * sc);
        }
        r[BR4[n1]] = s;
    }
    fft256_pass<true, true>(r, T[tx], j, -1.0f);

    const float SC = 1.0f / 4096.0f;
    if (do_store) {
#pragma unroll
        for (int k2 = 0; k2 < 8; ++k2)
            g_A[base + (unsigned)(j + 16 * k2) * (LL * LL)] =
                f2h(make_float2(r[k2].x * SC, r[k2].y * SC));
    }
}

// ---------------- Pass 4: inverse h-FFT (reads all h, writes h<128) ---------
__global__ void k_inv_h() {
    __shared__ float2 T[16][273];
    int tid = threadIdx.x;
    int tx = tid & 15, j = tid >> 4;
    unsigned x = blockIdx.x * 16 + tx, t = blockIdx.y, v = blockIdx.z;
    unsigned base = (v * LL + t) * LL * LL + x;
    float2 r[16];
#pragma unroll
    for (int n1 = 0; n1 < 16; ++n1)
        r[BR4[n1]] = h2f(g_A[base + (unsigned)(16 * n1 + j) * LL]);
    fft256_pass<false, true>(r, T[tx], j, -1.0f);
    const float SC = 1.0f / 4096.0f;
#pragma unroll
    for (int k2 = 0; k2 < 8; ++k2)
        g_A[base + (unsigned)(j + 16 * k2) * LL] =
            f2h(make_float2(r[k2].x * SC, r[k2].y * SC));
}

// ---------------- Pass 5: inverse x-FFT + real crop ------------------------
__global__ void k_inv_x(float* __restrict__ out) {
    __shared__ float2 T[16][273];
    int tid = threadIdx.x;
    int j = tid & 15, ln = tid >> 4;
    unsigned h = blockIdx.x * 16 + ln, t = blockIdx.y, v = blockIdx.z;
    unsigned base = ((v * LL + t) * LL + h) * LL;
    float2 r[16];
#pragma unroll
    for (int n1 = 0; n1 < 16; ++n1)
        r[BR4[n1]] = h2f(g_A[base + 16 * n1 + j]);
    fft256_pass<false, true>(r, T[ln], j, -1.0f);
    float* dst = out + (((v * 128u + t) * 128u + h) * 128u);
#pragma unroll
    for (int k2 = 0; k2 < 8; ++k2)
        dst[j + 16 * k2] = r[k2].x;
}

extern "C" void kernel_launch(void* const* d_in, const int* in_sizes, int n_in,
                              void* d_out, int out_size) {
    (void)in_sizes; (void)n_in; (void)out_size;
    const float* in = (const float*)d_in[0];
    float* out = (float*)d_out;

    k_fwd_x<<<dim3(8, 128, VOLS), 256>>>(in);
    k_fwd_h<<<dim3(9, 128, VOLS), 256>>>();
    k_t_samp_pair<<<dim3(16, 127, VOLS), 256>>>();
    k_t_samp_direct<<<dim3(16, 2, VOLS), 256>>>(0);
    k_t_samp_direct<<<dim3(1, 127, VOLS), 256>>>(1);
    k_inv_h<<<dim3(16, 128, VOLS), 256>>>();
    k_inv_x<<<dim3(8, 128, VOLS), 256>>>(out);
}

// round 17
// speedup vs baseline: 1.1287x; 1.0407x over previous
#include <cuda_runtime.h>
#include <cuda_fp16.h>
#include <cstdint>

// lct_fk round 17: R16 (164.6us) with the three t_samp launches merged into
// ONE kernel (grid.y = 130): y<127 Hermitian pair path, y=127/128 direct
// planes h=128/129 (all x), y=129 packed exception columns
// (h in {1,130..255}, x in {128,129}). Disjoint read/write sets verified;
// single-writer coverage identical to R16. fwd_x / fwd_h / inv_* unchanged.

#define LL 256u
#define VOLS 2

__device__ __half2 g_A[(size_t)VOLS * LL * LL * LL]; // 134 MB

__device__ const int BR4[16] = {0,8,4,12,2,10,6,14,1,9,5,13,3,11,7,15};

__device__ __forceinline__ float2 h2f(__half2 h) { return __half22float2(h); }
__device__ __forceinline__ __half2 f2h(float2 f) { return __floats2half2_rn(f.x, f.y); }

// ---------------- 16-pt in-register DIT FFT (input bit-reversed) ------------
template<bool ZIN, bool HOUT>
__device__ __forceinline__ void fft16x(float2 r[16], float dir) {
    const float CT[8] = {1.f, 0.92387953f, 0.70710678f, 0.38268343f,
                         0.f, -0.38268343f, -0.70710678f, -0.92387953f};
    const float ST[8] = {0.f, -0.38268343f, -0.70710678f, -0.92387953f,
                         -1.f, -0.92387953f, -0.70710678f, -0.38268343f};
    if (ZIN) {
#pragma unroll
        for (int m = 0; m < 8; ++m) r[2 * m + 1] = r[2 * m];
    } else {
#pragma unroll
        for (int m = 0; m < 8; ++m) {
            float2 a = r[2 * m], b = r[2 * m + 1];
            r[2 * m]     = make_float2(a.x + b.x, a.y + b.y);
            r[2 * m + 1] = make_float2(a.x - b.x, a.y - b.y);
        }
    }
#pragma unroll
    for (int s = 2; s <= 3; ++s) {
        int half = 1 << (s - 1);
#pragma unroll
        for (int j = 0; j < 8; ++j) {
            int k = j & (half - 1);
            int i0 = ((j >> (s - 1)) << s) + k;
            int i1 = i0 + half;
            float cs = CT[k << (4 - s)];
            float sn = dir * ST[k << (4 - s)];
            float2 b = r[i1];
            float tx = b.x * cs - b.y * sn;
            float ty = b.x * sn + b.y * cs;
            float2 a = r[i0];
            r[i1] = make_float2(a.x - tx, a.y - ty);
            r[i0] = make_float2(a.x + tx, a.y + ty);
        }
    }
#pragma unroll
    for (int j = 0; j < 8; ++j) {
        float cs = CT[j];
        float sn = dir * ST[j];
        float2 b = r[j + 8];
        float tx = b.x * cs - b.y * sn;
        float ty = b.x * sn + b.y * cs;
        float2 a = r[j];
        r[j] = make_float2(a.x + tx, a.y + ty);
        if (!HOUT) r[j + 8] = make_float2(a.x - tx, a.y - ty);
    }
}

// inter-pass twiddle via recurrence: r[k1] *= exp(dir * -2*pi*i * j*k1/256)
__device__ __forceinline__ void twiddle16(float2 r[16], int j, float dir) {
    float wy, wx;
    __sincosf(dir * -0.024543692606f * (float)j, &wy, &wx);
    float cx = wx, cy = wy;
#pragma unroll
    for (int k1 = 1; k1 < 16; ++k1) {
        float2 a = r[k1];
        r[k1] = make_float2(a.x * cx - a.y * cy, a.x * cy + a.y * cx);
        float nx = cx * wx - cy * wy;
        float ny = cx * wy + cy * wx;
        cx = nx; cy = ny;
    }
}

// Full 256-pt FFT for one line handled by 16 threads (role j).
template<bool ZIN, bool HOUT>
__device__ __forceinline__ void fft256_pass(float2 r[16], float2* Tline,
                                            int j, float dir) {
    fft16x<ZIN, false>(r, dir);
    twiddle16(r, j, dir);
    __syncthreads();
#pragma unroll
    for (int k1 = 0; k1 < 16; ++k1) Tline[k1 * 17 + j] = r[k1];
    __syncthreads();
    float2 rr[16];
#pragma unroll
    for (int n2 = 0; n2 < 16; ++n2) rr[BR4[n2]] = Tline[j * 17 + n2];
    fft16x<false, HOUT>(rr, dir);
#pragma unroll
    for (int k = 0; k < (HOUT ? 8 : 16); ++k) r[k] = rr[k];
}

// ---------------- Pass 1: preprocess + x-FFT + x-filter (kx<=129 only) ------
__global__ void k_fwd_x(const float* __restrict__ in) {
    __shared__ float2 T[16][273];
    int tid = threadIdx.x;
    int j = tid & 15, ln = tid >> 4;
    unsigned h = blockIdx.x * 16 + ln, t = blockIdx.y, v = blockIdx.z;
    float g = (float)t * (1.0f / 127.0f);
    const float* src = in + (((v * 128u + t) * 128u + h) * 128u);
    float2 r[16];
#pragma unroll
    for (int n1 = 0; n1 < 8; ++n1) {
        float f = src[16 * n1 + j];
        float xx = f * g * g;
        float val = (xx > 0.0f) ? sqrtf(xx) : 0.0f;
        r[BR4[n1]] = make_float2(val, 0.0f);
    }
    fft256_pass<true, false>(r, T[ln], j, 1.0f);
    __syncthreads();
#pragma unroll
    for (int k2 = 0; k2 < 16; ++k2) T[ln][j + 17 * k2] = r[k2];
    __syncthreads();
    __half2* __restrict__ dst = g_A + (((v * LL + t) * LL + h) * LL);
#pragma unroll
    for (int k2 = 0; k2 < 9; ++k2) {
        int k = j + 16 * k2;
        if (k > 129) continue;             // downstream reads only kx<=129
        float2 a = T[ln][k + (k >> 4)];
        float2 b = make_float2(0.f, 0.f);
        if (k != 128) { int km = (k - 1) & 255; b = T[ln][km + (km >> 4)]; }
        dst[k] = f2h(make_float2(0.5f * (a.x + b.x), 0.5f * (a.y + b.y)));
    }
}

// --- Pass 2: h-FFT for x in 0..143; base writes k<=129 (x=128/129: all k); --
// --- mirror columns x'=257-x (x in 2..127) written from same spectrum. ------
__global__ void k_fwd_h() {
    __shared__ float2 T[16][273];
    int tid = threadIdx.x;
    int tx = tid & 15, j = tid >> 4;
    unsigned x = blockIdx.x * 16 + tx;    // grid.x = 9 -> x in 0..143
    unsigned t = blockIdx.y, v = blockIdx.z;
    unsigned base = (v * LL + t) * LL * LL + x;
    float2 r[16];
#pragma unroll
    for (int n1 = 0; n1 < 8; ++n1)
        r[BR4[n1]] = h2f(g_A[base + (unsigned)(16 * n1 + j) * LL]);
    fft256_pass<true, false>(r, T[tx], j, 1.0f);
    __syncthreads();
#pragma unroll
    for (int k2 = 0; k2 < 16; ++k2) T[tx][j + 17 * k2] = r[k2]; // stash F
    __syncthreads();

    bool fullk = (x == 128u || x == 129u);
    bool basew = (x <= 129u);
#pragma unroll
    for (int k2 = 0; k2 < 16; ++k2) {
        int k = j + 16 * k2;
        bool wr = fullk || (basew && k <= 129);
        if (!wr) continue;
        float2 a = T[tx][k + (k >> 4)];
        float2 b = make_float2(0.f, 0.f);
        if (k != 128) { int km = (k - 1) & 255; b = T[tx][km + (km >> 4)]; }
        g_A[base + (unsigned)k * LL] =
            f2h(make_float2(0.5f * (a.x + b.x), 0.5f * (a.y + b.y)));
    }

    if (x >= 2u && x <= 127u) {           // emit mirror column x' = 257-x
        unsigned xm = 257u - x;           // 130..255
        unsigned baseM = (v * LL + t) * LL * LL + xm;
#pragma unroll
        for (int k2 = 0; k2 < 9; ++k2) {
            int kp = j + 16 * k2;
            if (kp > 129) continue;
            float2 val;
            if (kp <= 127) {
                int m = (257 - kp) & 255;
                int mm1 = (m - 1) & 255;
                float2 Fm = T[tx][m + (m >> 4)];
                float2 Fm1 = T[tx][mm1 + (mm1 >> 4)];
                val = make_float2(0.5f * (Fm.x + Fm1.x), -0.5f * (Fm.y + Fm1.y));
            } else if (kp == 128) {
                float2 F128 = T[tx][128 + 8];
                val = make_float2(0.5f * F128.x, -0.5f * F128.y);
            } else {                      // kp == 129
                float2 F127 = T[tx][127 + 7];
                float2 F128 = T[tx][128 + 8];
                val = make_float2(0.5f * (F127.x + F128.x),
                                  -0.5f * (F127.y + F128.y));
            }
            g_A[baseM + (unsigned)kp * LL] = f2h(val);
        }
    }
}

// ---- Pass 3 (merged): pair path (y<127) + direct exception paths (y>=127) --
__global__ void k_t_samp() {
    __shared__ float2 T[16][273];
    __shared__ float2 S2[16][137];
    int tid = threadIdx.x;
    int tx = tid & 15, j = tid >> 4;
    unsigned v = blockIdx.z;
    unsigned y = blockIdx.y;
    const float SC = 1.0f / 4096.0f;

    if (y < 127u) {
        // ======== pair path: base hb in {0,2..127}, mirror (257-hb,257-x) ===
        unsigned x = blockIdx.x * 16 + tx;
        unsigned hb = (y == 0) ? 0u : (y + 1u);
        unsigned base = v * LL * LL * LL + hb * LL + x;

        float2 r[16];
#pragma unroll
        for (int n1 = 0; n1 < 8; ++n1)
            r[BR4[n1]] = h2f(g_A[base + (unsigned)(16 * n1 + j) * (LL * LL)]);
        fft256_pass<true, false>(r, T[tx], j, 1.0f);
        __syncthreads();
#pragma unroll
        for (int k2 = 0; k2 < 16; ++k2) {
            int k = j + 16 * k2;
            T[tx][k + (k >> 4)] = r[k2];
        }
        __syncthreads();

        int iy = ((int)hb + 128) & 255;
        int ixs = ((int)x + 128) & 255;
        float gx = (float)(ixs - 128) * (1.0f / 128.0f);
        float gy = (float)(iy - 128) * (1.0f / 128.0f);
        float rxy = 0.1024f * (gx * gx + gy * gy);
        unsigned hm = (257u - hb) & 255u;
        unsigned xm = (257u - x) & 255u;
        int iym = ((int)hm + 128) & 255;
        int ixm = ((int)xm + 128) & 255;
        float gxm = (float)(ixm - 128) * (1.0f / 128.0f);
        float gym = (float)(iym - 128) * (1.0f / 128.0f);
        float rxym = 0.1024f * (gxm * gxm + gym * gym);

#pragma unroll
        for (int n1 = 0; n1 < 8; ++n1) {
            int t = 16 * n1 + j;
            float2 s = make_float2(0.f, 0.f);
            float2 sm = make_float2(0.f, 0.f);
            if (t >= 1) {
                float gz = (float)t * (1.0f / 128.0f);
                {   // base
                    float q = rxy + gz * gz;
                    float rq = rsqrtf(q);
                    float pzf = 128.0f * (q * rq) + 127.5f;
                    int z0 = (int)pzf;
                    float dz = pzf - (float)z0;
                    int p0 = z0 - 128, p1 = z0 - 127;
                    float sc = gz * rq;
                    float2 F0 = (p0 <= 127) ? T[tx][p0 + (p0 >> 4)] : make_float2(0.f, 0.f);
                    float2 F1 = (p1 <= 127) ? T[tx][p1 + (p1 >> 4)] : make_float2(0.f, 0.f);
                    s = make_float2((F0.x * (1.f - dz) + F1.x * dz) * sc,
                                    (F0.y * (1.f - dz) + F1.y * dz) * sc);
                }
                {   // mirror: F_mir[p] = conj(F[(256-p)&255]), own rxy
                    float q = rxym + gz * gz;
                    float rq = rsqrtf(q);
                    float pzf = 128.0f * (q * rq) + 127.5f;
                    int z0 = (int)pzf;
                    float dz = pzf - (float)z0;
                    int p0 = z0 - 128, p1 = z0 - 127;
                    float sc = gz * rq;
                    int m0 = (256 - p0) & 255;
                    int m1 = (256 - p1) & 255;
                    float2 F0 = (p0 <= 127) ? T[tx][m0 + (m0 >> 4)] : make_float2(0.f, 0.f);
                    float2 F1 = (p1 <= 127) ? T[tx][m1 + (m1 >> 4)] : make_float2(0.f, 0.f);
                    sm = make_float2((F0.x * (1.f - dz) + F1.x * dz) * sc,
                                     -(F0.y * (1.f - dz) + F1.y * dz) * sc);
                }
            }
            r[BR4[n1]] = s;
            S2[tx][t + (t >> 4)] = sm;
        }
        fft256_pass<true, true>(r, T[tx], j, -1.0f);
#pragma unroll
        for (int k2 = 0; k2 < 8; ++k2)
            g_A[base + (unsigned)(j + 16 * k2) * (LL * LL)] =
                f2h(make_float2(r[k2].x * SC, r[k2].y * SC));

#pragma unroll
        for (int n1 = 0; n1 < 8; ++n1) {
            int t = 16 * n1 + j;
            r[BR4[n1]] = S2[tx][t + (t >> 4)];
        }
        fft256_pass<true, true>(r, T[tx], j, -1.0f);
        if (x != 128u && x != 129u) {
            unsigned baseM = v * LL * LL * LL + hm * LL + xm;
#pragma unroll
            for (int k2 = 0; k2 < 8; ++k2)
                g_A[baseM + (unsigned)(j + 16 * k2) * (LL * LL)] =
                    f2h(make_float2(r[k2].x * SC, r[k2].y * SC));
        }
    } else {
        // ======== direct paths (exception columns) ==========================
        unsigned x, h;
        bool store;
        if (y < 129u) {                    // y=127 -> h=128, y=128 -> h=129
            h = y + 1u;
            x = blockIdx.x * 16 + tx;
            store = true;
        } else {                           // y=129: packed (h,x) exceptions
            int c = (int)(blockIdx.x * 16) + tx;   // 0..255
            int hidx = c >> 1;                     // 0..127
            h = (hidx == 0) ? 1u : (129u + (unsigned)hidx); // 1,130..255
            x = 128u + (unsigned)(c & 1);
            store = (c < 254);
            if (hidx > 126) h = 1u;                // clamp, store already off
        }
        unsigned base = v * LL * LL * LL + h * LL + x;

        float2 r[16];
#pragma unroll
        for (int n1 = 0; n1 < 8; ++n1)
            r[BR4[n1]] = h2f(g_A[base + (unsigned)(16 * n1 + j) * (LL * LL)]);
        fft256_pass<true, true>(r, T[tx], j, 1.0f);
        __syncthreads();
#pragma unroll
        for (int k2 = 0; k2 < 8; ++k2) {
            int k = j + 16 * k2;
            T[tx][k + (k >> 4)] = r[k2];
        }
        __syncthreads();

        int iy = ((int)h + 128) & 255;
        int ixs = ((int)x + 128) & 255;
        float gx = (float)(ixs - 128) * (1.0f / 128.0f);
        float gy = (float)(iy - 128) * (1.0f / 128.0f);
        float rxy = 0.1024f * (gx * gx + gy * gy);

#pragma unroll
        for (int n1 = 0; n1 < 8; ++n1) {
            int t = 16 * n1 + j;
            float2 s = make_float2(0.f, 0.f);
            if (t >= 1) {
                float gz = (float)t * (1.0f / 128.0f);
                float q = rxy + gz * gz;
                float rq = rsqrtf(q);
                float pzf = 128.0f * (q * rq) + 127.5f;
                int z0 = (int)pzf;
                float dz = pzf - (float)z0;
                int p0 = z0 - 128, p1 = z0 - 127;
                float2 S0 = (p0 <= 127) ? T[tx][p0 + (p0 >> 4)] : make_float2(0.f, 0.f);
                float2 S1 = (p1 <= 127) ? T[tx][p1 + (p1 >> 4)] : make_float2(0.f, 0.f);
                float sc = gz * rq;
                s = make_float2((S0.x * (1.f - dz) + S1.x * dz) * sc,
                                (S0.y * (1.f - dz) + S1.y * dz) * sc);
            }
            r[BR4[n1]] = s;
        }
        fft256_pass<true, true>(r, T[tx], j, -1.0f);
        if (store) {
#pragma unroll
            for (int k2 = 0; k2 < 8; ++k2)
                g_A[base + (unsigned)(j + 16 * k2) * (LL * LL)] =
                    f2h(make_float2(r[k2].x * SC, r[k2].y * SC));
        }
    }
}

// ---------------- Pass 4: inverse h-FFT (reads all h, writes h<128) ---------
__global__ void k_inv_h() {
    __shared__ float2 T[16][273];
    int tid = threadIdx.x;
    int tx = tid & 15, j = tid >> 4;
    unsigned x = blockIdx.x * 16 + tx, t = blockIdx.y, v = blockIdx.z;
    unsigned base = (v * LL + t) * LL * LL + x;
    float2 r[16];
#pragma unroll
    for (int n1 = 0; n1 < 16; ++n1)
        r[BR4[n1]] = h2f(g_A[base + (unsigned)(16 * n1 + j) * LL]);
    fft256_pass<false, true>(r, T[tx], j, -1.0f);
    const float SC = 1.0f / 4096.0f;
#pragma unroll
    for (int k2 = 0; k2 < 8; ++k2)
        g_A[base + (unsigned)(j + 16 * k2) * LL] =
            f2h(make_float2(r[k2].x * SC, r[k2].y * SC));
}

// ---------------- Pass 5: inverse x-FFT + real crop ------------------------
__global__ void k_inv_x(float* __restrict__ out) {
    __shared__ float2 T[16][273];
    int tid = threadIdx.x;
    int j = tid & 15, ln = tid >> 4;
    unsigned h = blockIdx.x * 16 + ln, t = blockIdx.y, v = blockIdx.z;
    unsigned base = ((v * LL + t) * LL + h) * LL;
    float2 r[16];
#pragma unroll
    for (int n1 = 0; n1 < 16; ++n1)
        r[BR4[n1]] = h2f(g_A[base + 16 * n1 + j]);
    fft256_pass<false, true>(r, T[ln], j, -1.0f);
    float* dst = out + (((v * 128u + t) * 128u + h) * 128u);
#pragma unroll
    for (int k2 = 0; k2 < 8; ++k2)
        dst[j + 16 * k2] = r[k2].x;
}

extern "C" void kernel_launch(void* const* d_in, const int* in_sizes, int n_in,
                              void* d_out, int out_size) {
    (void)in_sizes; (void)n_in; (void)out_size;
    const float* in = (const float*)d_in[0];
    float* out = (float*)d_out;

    k_fwd_x<<<dim3(8, 128, VOLS), 256>>>(in);
    k_fwd_h<<<dim3(9, 128, VOLS), 256>>>();
    k_t_samp<<<dim3(16, 130, VOLS), 256>>>();
    k_inv_h<<<dim3(16, 128, VOLS), 256>>>();
    k_inv_x<<<dim3(8, 128, VOLS), 256>>>(out);
}